// round 11
// baseline (speedup 1.0000x reference)
#include <cuda_runtime.h>
#include <cstdint>

#define R_   4
#define B_   512
#define T_   150
#define HD   32
#define K_   600
#define NK   160            // per-(r,b) correction-list capacity
#define X0   0.55f          // poly validity radius
#define T3c  (-0.33333333333f)
#define T5c  (0.13333333333f)
#define T7c  (-0.05396825397f)

// device intermediates
__device__ float g_attf[B_ * K_];
__device__ float g_G[R_ * B_ * 128];          // [(r*512+b)*128 + j*32 + c], j in {1,3,5,7}
__device__ float g_w1t[K_ * 128];             // W1 transposed [k][c]
__device__ int   g_klist[R_ * B_ * NK];
__device__ int   g_kn[R_ * B_];

// ---------------- helpers ----------------
__device__ __forceinline__ float tanha(float x) {
    float y; asm("tanh.approx.f32 %0, %1;" : "=f"(y) : "f"(x)); return y;
}
__device__ __forceinline__ unsigned long long pk2(float lo, float hi) {
    unsigned long long r;
    asm("mov.b64 %0, {%1, %2};" : "=l"(r) : "f"(lo), "f"(hi)); return r;
}
__device__ __forceinline__ void fma2(unsigned long long &acc,
                                     unsigned long long u, unsigned long long w) {
    asm("fma.rn.f32x2 %0, %1, %2, %0;" : "+l"(acc) : "l"(u), "l"(w));
}
__device__ __forceinline__ float2 up2(unsigned long long v) {
    float lo, hi;
    asm("mov.b64 {%0, %1}, %2;" : "=f"(lo), "=f"(hi) : "l"(v));
    return make_float2(lo, hi);
}

// ---------------- kernel G: G_j GEMMs + (x==32 plane) lists/W1T ----------------
// grid (33, 4), block 512. x<32: CTA computes G_j for 16 b's x 32 c. x==32: pre-pass.
// dyn smem: wcT[300][33] f32 | gp[16][300] float4   = 116400 bytes
#define G_SMEM 116400

__global__ __launch_bounds__(512, 1)
void camG(const float* __restrict__ feats,
          const float* __restrict__ a,
          const float* __restrict__ Wc,
          const float* __restrict__ W1)
{
    extern __shared__ float sm[];
    const int tid = threadIdx.x;
    const int r   = blockIdx.y;

    if (blockIdx.x == 32) {
        // -------- pre-pass plane --------
        const int w = tid >> 5, lane = tid & 31;
        const float ar = fabsf(__ldg(a + r));
        for (int b = w; b < B_; b += 16) {
            float m = 0.f;
            for (int t = lane; t < T_; t += 32)
                m = fmaxf(m, fabsf(__ldg(feats + (r * B_ + b) * T_ + t)));
            #pragma unroll
            for (int off = 16; off; off >>= 1)
                m = fmaxf(m, __shfl_xor_sync(0xffffffffu, m, off));
            const float xmax = ar * m;
            int base = 0;
            for (int k0 = 0; k0 < K_; k0 += 32) {
                int k = k0 + lane;
                float g = (k < K_) ? __ldg(feats + b * K_ + k) : 0.f;
                bool p = (k < K_) && (fabsf(g) * xmax > X0);
                unsigned mask = __ballot_sync(0xffffffffu, p);
                int pre = __popc(mask & ((1u << lane) - 1u));
                if (p && (base + pre) < NK)
                    g_klist[(r * B_ + b) * NK + base + pre] = k;
                base += __popc(mask);
            }
            if (lane == 0) g_kn[r * B_ + b] = base;   // >NK => H does full scan
        }
        if (r == 0) {  // W1 transpose (once)
            for (int i = tid; i < K_ * 128; i += 512) {
                int c = i / K_, k = i - c * K_;
                g_w1t[k * 128 + c] = __ldg(W1 + i);   // W1[c][k], coalesced read
            }
        }
        return;
    }

    // -------- G GEMM plane --------
    float*  wcT = sm;                          // [300][33]
    float4* gp  = (float4*)(sm + 300 * 33);    // [16][300]
    const int b0  = blockIdx.x * 16;
    const int b_l = tid >> 5;
    const int c   = tid & 31;

    unsigned long long A01 = 0ull, A23 = 0ull;   // (G1,G3), (G5,G7)

    for (int kc = 0; kc < K_; kc += 300) {
        __syncthreads();
        for (int i = tid; i < 32 * 300; i += 512) {
            int cc = i / 300, kk = i - cc * 300;
            wcT[kk * 33 + cc] = __ldg(Wc + (r * HD + cc) * K_ + kc + kk);
        }
        for (int i = tid; i < 16 * 300; i += 512) {
            int bb = i / 300, kk = i - bb * 300;
            float g  = __ldg(feats + (b0 + bb) * K_ + kc + kk);
            float g2 = g * g;
            float g3 = g * g2, g5 = g3 * g2, g7 = g5 * g2;
            gp[bb * 300 + kk] = make_float4(g, g3, g5, g7);
        }
        __syncthreads();
        #pragma unroll 4
        for (int kk = 0; kk < 300; kk++) {
            ulonglong2 gv = ((const ulonglong2*)gp)[b_l * 300 + kk];
            float wc = wcT[kk * 33 + c];
            unsigned long long wc2 = pk2(wc, wc);
            fma2(A01, gv.x, wc2);
            fma2(A23, gv.y, wc2);
        }
    }
    float2 s01 = up2(A01), s23 = up2(A23);
    int base = ((r * B_) + b0 + b_l) * 128 + c;
    g_G[base]      = s01.x;   // G1
    g_G[base + 32] = s01.y;   // G3
    g_G[base + 64] = s23.x;   // G5
    g_G[base + 96] = s23.y;   // G7
}

// ---------------- kernel H: poly assembly + sparse exact corrections ----------------
// grid (512 b, 4 r), block 160 (150 active rows)
__global__ __launch_bounds__(160)
void camH(const float* __restrict__ feats,
          const float* __restrict__ a,
          const float* __restrict__ W,
          const float* __restrict__ Wc,
          const float* __restrict__ Wh)
{
    __shared__ float Gq[128], gsh[K_], W_s[HD], Wh_s[HD];
    __shared__ int klist_s[NK];

    const int tid = threadIdx.x;
    const int b = blockIdx.x, r = blockIdx.y;

    for (int i = tid; i < K_; i += 160) gsh[i] = __ldg(feats + b * K_ + i);
    if (tid < 128) Gq[tid] = g_G[(r * B_ + b) * 128 + tid];
    if (tid < HD) { W_s[tid] = __ldg(W + r * HD + tid); Wh_s[tid] = __ldg(Wh + r * HD + tid); }
    const int kn = g_kn[r * B_ + b];
    for (int i = tid; i < min(kn, NK); i += 160) klist_s[i] = g_klist[(r * B_ + b) * NK + i];
    __syncthreads();

    if (tid >= T_) return;

    const float f = __ldg(feats + (r * B_ + b) * T_ + tid);
    const float x = __ldg(a + r) * f;
    const float x2 = x * x, x3 = x * x2, x5 = x3 * x2, x7 = x5 * x2;
    const float X1 = x, X3 = T3c * x3, X5 = T5c * x5, X7 = T7c * x7;

    float hm[HD];
    #pragma unroll
    for (int c = 0; c < HD; c++) {
        float s = X1 * Gq[c];
        s = fmaf(X3, Gq[32 + c], s);
        s = fmaf(X5, Gq[64 + c], s);
        s = fmaf(X7, Gq[96 + c], s);
        hm[c] = s;
    }

    // sparse exact corrections (loop indices warp-uniform -> broadcast loads)
    const int nIter = (kn <= NK) ? kn : K_;
    for (int i = 0; i < nIter; i++) {
        const int k = (kn <= NK) ? klist_s[i] : i;
        const float g = gsh[k];
        const float y = x * g;
        if (fabsf(y) > X0) {
            const float y2 = y * y;
            const float pl = y * fmaf(y2, fmaf(y2, fmaf(y2, T7c, T5c), T3c), 1.0f);
            const float d  = tanha(y) - pl;
            #pragma unroll
            for (int c = 0; c < HD; c++)
                hm[c] = fmaf(d, __ldg(Wc + (r * HD + c) * K_ + k), hm[c]);
        }
    }

    float attv = f;
    #pragma unroll
    for (int c = 0; c < HD; c++)
        attv = fmaf(fmaxf(fmaf(f, W_s[c], hm[c]), 0.0f), Wh_s[c], attv);

    g_attf[b * K_ + r * T_ + tid] = attv;
}

// ---------------- kernel B: MLP 600->128->7, coalesced W1T ----------------
// grid 128 (4 batches/CTA), block 256: thread = (khalf = tid>>7, b_l = (tid>>5)&3, c = tid&31)
__global__ __launch_bounds__(256)
void camB(const float* __restrict__ b1,
          const float* __restrict__ W2,
          const float* __restrict__ b2,
          float* __restrict__ out)
{
    __shared__ __align__(16) float v_s[4 * K_];
    __shared__ float part_s[2][4][128];
    __shared__ float h_s[4][128];

    const int bg  = blockIdx.x;
    const int tid = threadIdx.x;

    {
        const float4* src = (const float4*)(g_attf + bg * 4 * K_);
        for (int i = tid; i < K_; i += 256) ((float4*)v_s)[i] = src[i];
    }
    __syncthreads();

    const int kh  = tid >> 7;
    const int b_l = (tid >> 5) & 3;
    const int c   = tid & 31;

    {
        const float* vp = v_s + b_l * K_ + kh * 300;
        const float* wp = g_w1t + (kh * 300) * 128 + c;
        float a0 = 0.f, a1 = 0.f, a2 = 0.f, a3 = 0.f;
        #pragma unroll 4
        for (int kk = 0; kk < 300; kk++) {
            float v = vp[kk];                       // broadcast LDS
            const float* wrow = wp + kk * 128;      // 128B-coalesced LDG
            a0 = fmaf(v, __ldg(wrow),      a0);
            a1 = fmaf(v, __ldg(wrow + 32), a1);
            a2 = fmaf(v, __ldg(wrow + 64), a2);
            a3 = fmaf(v, __ldg(wrow + 96), a3);
        }
        part_s[kh][b_l][c]      = a0;
        part_s[kh][b_l][c + 32] = a1;
        part_s[kh][b_l][c + 64] = a2;
        part_s[kh][b_l][c + 96] = a3;
    }
    __syncthreads();

    {
        const int cc = tid & 127, j0 = tid >> 7;
        #pragma unroll
        for (int j = j0; j < 4; j += 2)
            h_s[j][cc] = part_s[0][j][cc] + part_s[1][j][cc] + __ldg(b1 + cc);
    }
    __syncthreads();

    if (tid < 28) {
        const int j = tid / 7, o = tid - j * 7;
        float s = __ldg(b2 + o);
        #pragma unroll 8
        for (int cc = 0; cc < 128; cc++)
            s = fmaf(__ldg(W2 + o * 128 + cc), h_s[j][cc], s);
        out[(bg * 4 + j) * 7 + o] = s;
    }
}

// ---------------- launch ----------------
extern "C" void kernel_launch(void* const* d_in, const int* in_sizes, int n_in,
                              void* d_out, int out_size)
{
    const float* feats = (const float*)d_in[0];
    const float* a     = (const float*)d_in[1];
    const float* W     = (const float*)d_in[2];
    const float* Wc    = (const float*)d_in[3];
    const float* Wh    = (const float*)d_in[4];
    const float* W1    = (const float*)d_in[5];
    const float* b1    = (const float*)d_in[6];
    const float* W2    = (const float*)d_in[7];
    const float* b2    = (const float*)d_in[8];
    float* out = (float*)d_out;

    cudaFuncSetAttribute(camG, cudaFuncAttributeMaxDynamicSharedMemorySize, G_SMEM);

    camG<<<dim3(33, 4), 512, G_SMEM>>>(feats, a, Wc, W1);
    camH<<<dim3(B_, R_), 160>>>(feats, a, W, Wc, Wh);
    camB<<<B_ / 4, 256>>>(b1, W2, b2, out);
}

// round 12
// speedup vs baseline: 2.0278x; 2.0278x over previous
#include <cuda_runtime.h>
#include <cstdint>

#define R_   4
#define B_   512
#define T_   150
#define HD   32
#define K_   600
#define NK   160            // per-(r,b) correction-list capacity
#define X0   0.55f          // poly validity radius
#define T3c  (-0.33333333333f)
#define T5c  (0.13333333333f)
#define T7c  (-0.05396825397f)

// device intermediates
__device__ float g_G[R_ * B_ * 128];          // [(r*512+b)*128 + j*32 + c], j in {1,3,5,7}
__device__ float g_w1t[K_ * 128];             // W1 transposed [k][c]
__device__ int   g_klist[R_ * B_ * NK];
__device__ int   g_kn[R_ * B_];

// ---------------- helpers ----------------
__device__ __forceinline__ float tanha(float x) {
    float y; asm("tanh.approx.f32 %0, %1;" : "=f"(y) : "f"(x)); return y;
}
__device__ __forceinline__ unsigned long long pk2(float lo, float hi) {
    unsigned long long r;
    asm("mov.b64 %0, {%1, %2};" : "=l"(r) : "f"(lo), "f"(hi)); return r;
}
__device__ __forceinline__ void fma2(unsigned long long &acc,
                                     unsigned long long u, unsigned long long w) {
    asm("fma.rn.f32x2 %0, %1, %2, %0;" : "+l"(acc) : "l"(u), "l"(w));
}
__device__ __forceinline__ float2 up2(unsigned long long v) {
    float lo, hi;
    asm("mov.b64 {%0, %1}, %2;" : "=f"(lo), "=f"(hi) : "l"(v));
    return make_float2(lo, hi);
}

// ---------------- kernel G: grid (37,4) = 148 CTAs, one wave ----------------
//   x <  32 : G_j GEMM, 16 b's x 32 c per CTA
//   x 32-35 : correction-list pre-pass (64 warps per r, 8 b's/warp, prefetched)
//   x == 36 : W1 transpose (r-split)
// dyn smem (GEMM plane): wcT[300][33] f32 | gp[16][300] float4  = 116400 B
#define G_SMEM 116400

__global__ __launch_bounds__(512, 1)
void camG(const float* __restrict__ feats,
          const float* __restrict__ a,
          const float* __restrict__ Wc,
          const float* __restrict__ W1)
{
    extern __shared__ float sm[];
    const int tid = threadIdx.x;
    const int r   = blockIdx.y;
    const int bx  = blockIdx.x;

    if (bx >= 32) {
        if (bx == 36) {
            // ---- W1 transpose plane: CTA r handles c in [r*32, r*32+32) ----
            for (int i = tid; i < 32 * K_; i += 512) {
                int c_l = i / K_;
                int k   = i - c_l * K_;
                g_w1t[k * 128 + r * 32 + c_l] = __ldg(W1 + (r * 32 + c_l) * K_ + k);
            }
            return;
        }
        // ---- list pre-pass plane p = bx-32 (0..3); warp handles 8 b's ----
        const int p = bx - 32;
        const int w = tid >> 5, lane = tid & 31;
        const float ar = fabsf(__ldg(a + r));
        #pragma unroll 1
        for (int i = 0; i < 8; i++) {
            const int b = p * 16 + w + 64 * i;
            // T-max (5 independent loads)
            float m = 0.f;
            #pragma unroll
            for (int it = 0; it < 5; it++) {
                int t = it * 32 + lane;
                if (t < T_) m = fmaxf(m, fabsf(__ldg(feats + (r * B_ + b) * T_ + t)));
            }
            #pragma unroll
            for (int off = 16; off; off >>= 1)
                m = fmaxf(m, __shfl_xor_sync(0xffffffffu, m, off));
            const float xmax = ar * m;
            // prefetch all g values (independent loads, MLP=19)
            float gk[19];
            #pragma unroll
            for (int it = 0; it < 19; it++) {
                int k = it * 32 + lane;
                gk[it] = (k < K_) ? __ldg(feats + b * K_ + k) : 0.f;
            }
            // ballot chain (no loads inside)
            int base = 0;
            #pragma unroll
            for (int it = 0; it < 19; it++) {
                int k = it * 32 + lane;
                bool pq = (k < K_) && (fabsf(gk[it]) * xmax > X0);
                unsigned mask = __ballot_sync(0xffffffffu, pq);
                int pre = __popc(mask & ((1u << lane) - 1u));
                if (pq && (base + pre) < NK)
                    g_klist[(r * B_ + b) * NK + base + pre] = k;
                base += __popc(mask);
            }
            if (lane == 0) g_kn[r * B_ + b] = base;   // >NK => full scan downstream
        }
        return;
    }

    // ---- G GEMM plane (validated in r11) ----
    float*  wcT = sm;                          // [300][33]
    float4* gp  = (float4*)(sm + 300 * 33);    // [16][300]
    const int b0  = bx * 16;
    const int b_l = tid >> 5;
    const int c   = tid & 31;

    unsigned long long A01 = 0ull, A23 = 0ull;   // (G1,G3), (G5,G7)

    for (int kc = 0; kc < K_; kc += 300) {
        __syncthreads();
        for (int i = tid; i < 32 * 300; i += 512) {
            int cc = i / 300, kk = i - cc * 300;
            wcT[kk * 33 + cc] = __ldg(Wc + (r * HD + cc) * K_ + kc + kk);
        }
        for (int i = tid; i < 16 * 300; i += 512) {
            int bb = i / 300, kk = i - bb * 300;
            float g  = __ldg(feats + (b0 + bb) * K_ + kc + kk);
            float g2 = g * g;
            float g3 = g * g2, g5 = g3 * g2, g7 = g5 * g2;
            gp[bb * 300 + kk] = make_float4(g, g3, g5, g7);
        }
        __syncthreads();
        #pragma unroll 4
        for (int kk = 0; kk < 300; kk++) {
            ulonglong2 gv = ((const ulonglong2*)gp)[b_l * 300 + kk];
            float wc = wcT[kk * 33 + c];
            unsigned long long wc2 = pk2(wc, wc);
            fma2(A01, gv.x, wc2);
            fma2(A23, gv.y, wc2);
        }
    }
    float2 s01 = up2(A01), s23 = up2(A23);
    int base = ((r * B_) + b0 + b_l) * 128 + c;
    g_G[base]      = s01.x;   // G1
    g_G[base + 32] = s01.y;   // G3
    g_G[base + 64] = s23.x;   // G5
    g_G[base + 96] = s23.y;   // G7
}

// ---------------- kernel HB: fused poly-assembly + corrections + MLP ----------------
// grid 128 (4 b's per CTA), block 512.
__global__ __launch_bounds__(512)
void camHB(const float* __restrict__ feats,
           const float* __restrict__ a,
           const float* __restrict__ W,
           const float* __restrict__ Wc,
           const float* __restrict__ Wh,
           const float* __restrict__ b1,
           const float* __restrict__ W2,
           const float* __restrict__ b2,
           float* __restrict__ out)
{
    __shared__ float gsh[4][K_];        // feat_n rows of the 4 b's
    __shared__ float vsh[4][K_];        // attf results (r*150+t order)
    __shared__ float Gq[16][128];       // [jb*4+r]
    __shared__ float Wsh[4][32], Whsh[4][32];
    __shared__ float ash[4];
    __shared__ int   klist_s[16][NK];
    __shared__ int   kn_s[16];
    __shared__ float h_s[4][128];

    const int bg  = blockIdx.x;
    const int tid = threadIdx.x;

    // ---- staging ----
    for (int i = tid; i < 4 * K_; i += 512) {
        int jb = i / K_, k = i - jb * K_;
        gsh[jb][k] = __ldg(feats + (bg * 4 + jb) * K_ + k);
    }
    for (int i = tid; i < 2048; i += 512) {
        int q = i >> 7, c = i & 127;
        int jb = q >> 2, rr = q & 3;
        Gq[q][c] = g_G[(rr * B_ + bg * 4 + jb) * 128 + c];
    }
    if (tid < 128) {
        int rr = tid >> 5, c = tid & 31;
        Wsh[rr][c]  = __ldg(W  + rr * HD + c);
        Whsh[rr][c] = __ldg(Wh + rr * HD + c);
    }
    if (tid < 4) ash[tid] = __ldg(a + tid);
    if (tid < 16) {
        int jb = tid >> 2, rr = tid & 3;
        kn_s[tid] = g_kn[rr * B_ + bg * 4 + jb];
    }
    for (int i = tid; i < 16 * NK; i += 512) {
        int q = i / NK, idx = i - q * NK;
        int jb = q >> 2, rr = q & 3;
        klist_s[q][idx] = g_klist[(rr * B_ + bg * 4 + jb) * NK + idx];
    }
    __syncthreads();

    // ---- row phase: 2400 rows = (jb, r, t) ----
    #pragma unroll 1
    for (int row = tid; row < 2400; row += 512) {
        const int jb  = row / 600;
        const int rem = row - jb * 600;
        const int rr  = rem / 150;
        const int t   = rem - rr * 150;
        const int b   = bg * 4 + jb;
        const int q   = jb * 4 + rr;

        const float f = __ldg(feats + (rr * B_ + b) * T_ + t);
        const float x = ash[rr] * f;
        const float x2 = x * x, x3 = x * x2, x5 = x3 * x2, x7 = x5 * x2;
        const float X1 = x, X3 = T3c * x3, X5 = T5c * x5, X7 = T7c * x7;

        float hm[HD];
        #pragma unroll
        for (int c = 0; c < HD; c++) {
            float s = X1 * Gq[q][c];
            s = fmaf(X3, Gq[q][32 + c], s);
            s = fmaf(X5, Gq[q][64 + c], s);
            s = fmaf(X7, Gq[q][96 + c], s);
            hm[c] = s;
        }

        const int kn = kn_s[q];
        const int nIter = (kn <= NK) ? kn : K_;
        for (int i = 0; i < nIter; i++) {
            const int k = (kn <= NK) ? klist_s[q][i] : i;
            const float g = gsh[jb][k];
            const float y = x * g;
            if (fabsf(y) > X0) {
                const float y2 = y * y;
                const float pl = y * fmaf(y2, fmaf(y2, fmaf(y2, T7c, T5c), T3c), 1.0f);
                const float d  = tanha(y) - pl;
                #pragma unroll
                for (int c = 0; c < HD; c++)
                    hm[c] = fmaf(d, __ldg(Wc + (rr * HD + c) * K_ + k), hm[c]);
            }
        }

        float attv = f;
        #pragma unroll
        for (int c = 0; c < HD; c++)
            attv = fmaf(fmaxf(fmaf(f, Wsh[rr][c], hm[c]), 0.0f), Whsh[rr][c], attv);

        vsh[jb][rr * T_ + t] = attv;
    }
    __syncthreads();

    // ---- MLP: thread = (jb = tid>>7, c = tid&127) ----
    {
        const int jb = tid >> 7;
        const int c  = tid & 127;
        float acc = 0.f;
        #pragma unroll 4
        for (int k = 0; k < K_; k++)
            acc = fmaf(vsh[jb][k], __ldg(g_w1t + k * 128 + c), acc);
        h_s[jb][c] = acc + __ldg(b1 + c);
    }
    __syncthreads();

    if (tid < 28) {
        const int j = tid / 7, o = tid - j * 7;
        float s = __ldg(b2 + o);
        #pragma unroll 8
        for (int cc = 0; cc < 128; cc++)
            s = fmaf(__ldg(W2 + o * 128 + cc), h_s[j][cc], s);
        out[(bg * 4 + j) * 7 + o] = s;
    }
}

// ---------------- launch ----------------
extern "C" void kernel_launch(void* const* d_in, const int* in_sizes, int n_in,
                              void* d_out, int out_size)
{
    const float* feats = (const float*)d_in[0];
    const float* a     = (const float*)d_in[1];
    const float* W     = (const float*)d_in[2];
    const float* Wc    = (const float*)d_in[3];
    const float* Wh    = (const float*)d_in[4];
    const float* W1    = (const float*)d_in[5];
    const float* b1    = (const float*)d_in[6];
    const float* W2    = (const float*)d_in[7];
    const float* b2    = (const float*)d_in[8];
    float* out = (float*)d_out;

    cudaFuncSetAttribute(camG, cudaFuncAttributeMaxDynamicSharedMemorySize, G_SMEM);

    camG<<<dim3(37, 4), 512, G_SMEM>>>(feats, a, Wc, W1);
    camHB<<<128, 512>>>(feats, a, W, Wc, Wh, b1, W2, b2, out);
}